// round 4
// baseline (speedup 1.0000x reference)
#include <cuda_runtime.h>

// MLP_89498528514757 — fused recommender MLP, fp32. Round 4:
// 128 blocks x 512 threads (one wave). Layer 2: 64 j-groups x 8-way split-K,
// 2 j-columns x 8 rows per thread (16 FFMA per 4 mem ops). Conflict-free
// row-half-major smem layouts; h2p/h3p partials share one 32KB union.

#define NUM_USERS 100000
#define BATCH     1024
#define ROWS      8

__global__ __launch_bounds__(512)
void mlp_fused_kernel(const int*   __restrict__ user_ids,
                      const int*   __restrict__ item_ids,
                      const float* __restrict__ W1, const float* __restrict__ b1,
                      const float* __restrict__ W2, const float* __restrict__ b2,
                      const float* __restrict__ W3, const float* __restrict__ b3,
                      const float* __restrict__ W4, const float* __restrict__ b4,
                      float*       __restrict__ out)
{
    __shared__ float4 h1t[2][256];                 // [rowhalf][k]   8 KB
    __shared__ union {
        float l2[8][8][128];                       // [ks][row][j]  32 KB
        float l3[8][8][64];                        // [ks][row][j]  16 KB
    } P;
    __shared__ float4 h2t[2][128];                 // [rowhalf][k]   4 KB
    __shared__ float4 h3t[2][64];                  // [rowhalf][j]   2 KB

    const int t    = threadIdx.x;                  // 0..511
    const int row0 = blockIdx.x * ROWS;

    // ---------------- Layer 1: start the dependent DRAM chain FIRST --------
    const int k1  = t & 255;
    const int rh1 = t >> 8;                        // 0 or 1
    const int rb  = row0 + rh1 * 4;
    const int u0 = user_ids[rb + 0], i0 = item_ids[rb + 0];
    const int u1 = user_ids[rb + 1], i1 = item_ids[rb + 1];
    const int u2 = user_ids[rb + 2], i2 = item_ids[rb + 2];
    const int u3 = user_ids[rb + 3], i3 = item_ids[rb + 3];
    const float g0 = W1[u0 * 256 + k1], e0 = W1[(NUM_USERS + i0) * 256 + k1];
    const float g1 = W1[u1 * 256 + k1], e1 = W1[(NUM_USERS + i1) * 256 + k1];
    const float g2 = W1[u2 * 256 + k1], e2 = W1[(NUM_USERS + i2) * 256 + k1];
    const float g3 = W1[u3 * 256 + k1], e3 = W1[(NUM_USERS + i3) * 256 + k1];

    // ---- overlap: biases + layer-2 weight prefetch while gather in flight --
    const int jg = t & 63;                         // layer-2 j-group: j = jg, jg+64
    const int ks = t >> 6;                         // 0..7 k-split
    const int kb = ks * 32;                        // k-base (32 iters)
    const float* __restrict__ w2pa = W2 + kb * 128 + jg;
    const float* __restrict__ w2pb = w2pa + 64;
    float w2prea[8], w2preb[8];
    #pragma unroll
    for (int i = 0; i < 8; ++i) { w2prea[i] = w2pa[i * 128]; w2preb[i] = w2pb[i * 128]; }

    const float bj2 = b2[t & 127];
    const float bj3 = b3[jg];
    float w4a = 0.f, w4b = 0.f, bb4 = 0.f;
    if (t < 32) { w4a = W4[t]; w4b = W4[t + 32]; bb4 = b4[0]; }

    // finish layer 1
    {
        const float bk = b1[k1];
        float4 h;
        h.x = fmaxf(g0 + e0 + bk, 0.f);
        h.y = fmaxf(g1 + e1 + bk, 0.f);
        h.z = fmaxf(g2 + e2 + bk, 0.f);
        h.w = fmaxf(g3 + e3 + bk, 0.f);
        h1t[rh1][k1] = h;                          // conflict-free STS.128
    }
    __syncthreads();

    // ---------------- Layer 2: [8x256] @ W2[256x128], 8-way K, 2 j/thread --
    {
        float4 a00 = make_float4(0.f,0.f,0.f,0.f), a01 = a00;  // j=jg    rows 0-3, 4-7
        float4 a10 = a00, a11 = a00;                            // j=jg+64
        #pragma unroll
        for (int kk = 0; kk < 8; ++kk) {           // prefetched weights
            const int k = kb + kk;
            const float wa = w2prea[kk], wb = w2preb[kk];
            const float4 va = h1t[0][k], vb = h1t[1][k];
            a00.x = fmaf(va.x, wa, a00.x); a00.y = fmaf(va.y, wa, a00.y);
            a00.z = fmaf(va.z, wa, a00.z); a00.w = fmaf(va.w, wa, a00.w);
            a01.x = fmaf(vb.x, wa, a01.x); a01.y = fmaf(vb.y, wa, a01.y);
            a01.z = fmaf(vb.z, wa, a01.z); a01.w = fmaf(vb.w, wa, a01.w);
            a10.x = fmaf(va.x, wb, a10.x); a10.y = fmaf(va.y, wb, a10.y);
            a10.z = fmaf(va.z, wb, a10.z); a10.w = fmaf(va.w, wb, a10.w);
            a11.x = fmaf(vb.x, wb, a11.x); a11.y = fmaf(vb.y, wb, a11.y);
            a11.z = fmaf(vb.z, wb, a11.z); a11.w = fmaf(vb.w, wb, a11.w);
        }
        #pragma unroll
        for (int kk = 8; kk < 32; ++kk) {
            const int k = kb + kk;
            const float wa = w2pa[kk * 128], wb = w2pb[kk * 128];
            const float4 va = h1t[0][k], vb = h1t[1][k];
            a00.x = fmaf(va.x, wa, a00.x); a00.y = fmaf(va.y, wa, a00.y);
            a00.z = fmaf(va.z, wa, a00.z); a00.w = fmaf(va.w, wa, a00.w);
            a01.x = fmaf(vb.x, wa, a01.x); a01.y = fmaf(vb.y, wa, a01.y);
            a01.z = fmaf(vb.z, wa, a01.z); a01.w = fmaf(vb.w, wa, a01.w);
            a10.x = fmaf(va.x, wb, a10.x); a10.y = fmaf(va.y, wb, a10.y);
            a10.z = fmaf(va.z, wb, a10.z); a10.w = fmaf(va.w, wb, a10.w);
            a11.x = fmaf(vb.x, wb, a11.x); a11.y = fmaf(vb.y, wb, a11.y);
            a11.z = fmaf(vb.z, wb, a11.z); a11.w = fmaf(vb.w, wb, a11.w);
        }
        // partials: lane index = jg contiguous -> conflict-free STS.32
        P.l2[ks][0][jg] = a00.x;  P.l2[ks][1][jg] = a00.y;
        P.l2[ks][2][jg] = a00.z;  P.l2[ks][3][jg] = a00.w;
        P.l2[ks][4][jg] = a01.x;  P.l2[ks][5][jg] = a01.y;
        P.l2[ks][6][jg] = a01.z;  P.l2[ks][7][jg] = a01.w;
        P.l2[ks][0][jg+64] = a10.x;  P.l2[ks][1][jg+64] = a10.y;
        P.l2[ks][2][jg+64] = a10.z;  P.l2[ks][3][jg+64] = a10.w;
        P.l2[ks][4][jg+64] = a11.x;  P.l2[ks][5][jg+64] = a11.y;
        P.l2[ks][6][jg+64] = a11.z;  P.l2[ks][7][jg+64] = a11.w;
    }

    // ---- layer-3 weight prefetch before the sync (16 iters, all in regs) --
    float w3pre[16];
    {
        const float* __restrict__ w3p = W3 + (ks * 16) * 64 + jg;
        #pragma unroll
        for (int i = 0; i < 16; ++i) w3pre[i] = w3p[i * 64];
    }
    __syncthreads();

    // combine layer-2 partials with all 512 threads: j = t&127, rowhalf = t>>7&1
    {
        const int j  = t & 127;
        const int rh = (t >> 7) & 1;               // threads 256..511 duplicate rh
        if (t < 256) {
            float s0 = bj2, s1 = bj2, s2 = bj2, s3 = bj2;
            #pragma unroll
            for (int s = 0; s < 8; ++s) {
                s0 += P.l2[s][rh * 4 + 0][j];
                s1 += P.l2[s][rh * 4 + 1][j];
                s2 += P.l2[s][rh * 4 + 2][j];
                s3 += P.l2[s][rh * 4 + 3][j];
            }
            h2t[rh][j] = make_float4(fmaxf(s0, 0.f), fmaxf(s1, 0.f),
                                     fmaxf(s2, 0.f), fmaxf(s3, 0.f));
        }
    }
    __syncthreads();

    // ---------------- Layer 3: [8x128] @ W3[128x64], 8-way split-K ---------
    {
        float4 a0 = make_float4(0.f,0.f,0.f,0.f), a1 = a0;
        #pragma unroll
        for (int kk = 0; kk < 16; ++kk) {
            const int k = ks * 16 + kk;
            const float w = w3pre[kk];
            const float4 va = h2t[0][k], vb = h2t[1][k];
            a0.x = fmaf(va.x, w, a0.x);  a0.y = fmaf(va.y, w, a0.y);
            a0.z = fmaf(va.z, w, a0.z);  a0.w = fmaf(va.w, w, a0.w);
            a1.x = fmaf(vb.x, w, a1.x);  a1.y = fmaf(vb.y, w, a1.y);
            a1.z = fmaf(vb.z, w, a1.z);  a1.w = fmaf(vb.w, w, a1.w);
        }
        P.l3[ks][0][jg] = a0.x;  P.l3[ks][1][jg] = a0.y;
        P.l3[ks][2][jg] = a0.z;  P.l3[ks][3][jg] = a0.w;
        P.l3[ks][4][jg] = a1.x;  P.l3[ks][5][jg] = a1.y;
        P.l3[ks][6][jg] = a1.z;  P.l3[ks][7][jg] = a1.w;
    }
    __syncthreads();

    // combine layer-3 partials: 128 threads, j = t&63, rowhalf = t>>6
    if (t < 128) {
        const int j  = t & 63;
        const int rh = t >> 6;
        float s0 = bj3, s1 = bj3, s2 = bj3, s3 = bj3;
        #pragma unroll
        for (int s = 0; s < 8; ++s) {
            s0 += P.l3[s][rh * 4 + 0][j];
            s1 += P.l3[s][rh * 4 + 1][j];
            s2 += P.l3[s][rh * 4 + 2][j];
            s3 += P.l3[s][rh * 4 + 3][j];
        }
        h3t[rh][j] = make_float4(fmaxf(s0, 0.f), fmaxf(s1, 0.f),
                                 fmaxf(s2, 0.f), fmaxf(s3, 0.f));
    }
    __syncthreads();

    // ---------------- Layer 4: [8x64] @ W4[64x1] + b4 (warp 0) -------------
    if (t < 32) {
        const float4 va0 = h3t[0][t],      va1 = h3t[1][t];
        const float4 vb0 = h3t[0][t + 32], vb1 = h3t[1][t + 32];
        float a0 = fmaf(va0.x, w4a, vb0.x * w4b);
        float a1 = fmaf(va0.y, w4a, vb0.y * w4b);
        float a2 = fmaf(va0.z, w4a, vb0.z * w4b);
        float a3 = fmaf(va0.w, w4a, vb0.w * w4b);
        float a4 = fmaf(va1.x, w4a, vb1.x * w4b);
        float a5 = fmaf(va1.y, w4a, vb1.y * w4b);
        float a6 = fmaf(va1.z, w4a, vb1.z * w4b);
        float a7 = fmaf(va1.w, w4a, vb1.w * w4b);
        #pragma unroll
        for (int off = 16; off > 0; off >>= 1) {
            a0 += __shfl_down_sync(0xffffffffu, a0, off);
            a1 += __shfl_down_sync(0xffffffffu, a1, off);
            a2 += __shfl_down_sync(0xffffffffu, a2, off);
            a3 += __shfl_down_sync(0xffffffffu, a3, off);
            a4 += __shfl_down_sync(0xffffffffu, a4, off);
            a5 += __shfl_down_sync(0xffffffffu, a5, off);
            a6 += __shfl_down_sync(0xffffffffu, a6, off);
            a7 += __shfl_down_sync(0xffffffffu, a7, off);
        }
        if (t == 0) {
            out[row0 + 0] = a0 + bb4;  out[row0 + 1] = a1 + bb4;
            out[row0 + 2] = a2 + bb4;  out[row0 + 3] = a3 + bb4;
            out[row0 + 4] = a4 + bb4;  out[row0 + 5] = a5 + bb4;
            out[row0 + 6] = a6 + bb4;  out[row0 + 7] = a7 + bb4;
        }
    }
}

extern "C" void kernel_launch(void* const* d_in, const int* in_sizes, int n_in,
                              void* d_out, int out_size)
{
    const int*   user_ids = (const int*)  d_in[0];
    const int*   item_ids = (const int*)  d_in[1];
    const float* W1       = (const float*)d_in[2];
    const float* b1       = (const float*)d_in[3];
    const float* W2       = (const float*)d_in[4];
    const float* b2       = (const float*)d_in[5];
    const float* W3       = (const float*)d_in[6];
    const float* b3       = (const float*)d_in[7];
    const float* W4       = (const float*)d_in[8];
    const float* b4       = (const float*)d_in[9];
    float*       out      = (float*)d_out;

    mlp_fused_kernel<<<BATCH / ROWS, 512>>>(user_ids, item_ids,
                                            W1, b1, W2, b2, W3, b3, W4, b4, out);
}

// round 5
// speedup vs baseline: 1.0269x; 1.0269x over previous
#include <cuda_runtime.h>

// MLP_89498528514757 — fused recommender MLP, fp32. Round 5:
// R3 structure, but ROWS=4 / grid 256 x 512 threads with
// __launch_bounds__(512,2): 2 co-resident blocks per SM (occ 50%) so
// barrier/gather stalls of one block are hidden by the other, and no SM
// is idle (R3's grid=128 left 20 SMs empty).

#define NUM_USERS 100000
#define BATCH     1024
#define ROWS      4

__global__ __launch_bounds__(512, 2)
void mlp_fused_kernel(const int*   __restrict__ user_ids,
                      const int*   __restrict__ item_ids,
                      const float* __restrict__ W1, const float* __restrict__ b1,
                      const float* __restrict__ W2, const float* __restrict__ b2,
                      const float* __restrict__ W3, const float* __restrict__ b3,
                      const float* __restrict__ W4, const float* __restrict__ b4,
                      float*       __restrict__ out)
{
    __shared__ float4 h1t[256];      // h1[k], 4 rows       (4 KB)
    __shared__ float4 h2p[512];      // layer-2 partials     (8 KB)
    __shared__ float4 h2t[128];      // h2[k], 4 rows        (2 KB)
    __shared__ float4 h3p[512];      // layer-3 partials     (8 KB)
    __shared__ float4 h3t[64];       // h3[j], 4 rows        (1 KB)

    const int t    = threadIdx.x;    // 0..511
    const int row0 = blockIdx.x * ROWS;

    // ---------------- Layer 1: start the dependent DRAM chain FIRST --------
    // Thread t: feature k = t&255, pair g = t>>8 owns rows {2g, 2g+1}.
    const int k1 = t & 255;
    const int g  = t >> 8;                        // 0 or 1
    const int ra = row0 + g * 2, rbw = ra + 1;
    const int ua = user_ids[ra],  ia = item_ids[ra];
    const int ub = user_ids[rbw], ib = item_ids[rbw];
    const float ga = W1[ua * 256 + k1], ea = W1[(NUM_USERS + ia) * 256 + k1];
    const float gb = W1[ub * 256 + k1], eb = W1[(NUM_USERS + ib) * 256 + k1];

    // ---- overlap: biases + layer-2 weight prefetch while gather in flight --
    const int j2  = t & 127;
    const int kq2 = t >> 7;                       // 0..3 (k-quarter, 64 iters)
    const float* __restrict__ w2p = W2 + (kq2 * 64) * 128 + j2;
    float w2pre[16];
    #pragma unroll
    for (int i = 0; i < 16; ++i) w2pre[i] = w2p[i * 128];

    const float bj2 = b2[j2];
    const float bj3 = b3[t & 63];
    float w4a = 0.f, w4b = 0.f, bb4 = 0.f;
    if (t < 32) { w4a = W4[t]; w4b = W4[t + 32]; bb4 = b4[0]; }

    // finish layer 1: each thread writes its 2 rows (8B STS)
    {
        const float bk = b1[k1];
        float2 h;
        h.x = fmaxf(ga + ea + bk, 0.f);
        h.y = fmaxf(gb + eb + bk, 0.f);
        *reinterpret_cast<float2*>(
            reinterpret_cast<float*>(&h1t[k1]) + g * 2) = h;
    }
    __syncthreads();

    // ---------------- Layer 2: [4 x 256] @ W2[256 x 128], 4-way split-K ----
    {
        float4 a = make_float4(0.f, 0.f, 0.f, 0.f);
        #pragma unroll
        for (int kk = 0; kk < 16; ++kk) {         // prefetched weights
            const float  w = w2pre[kk];
            const float4 v = h1t[kq2 * 64 + kk];
            a.x = fmaf(v.x, w, a.x);  a.y = fmaf(v.y, w, a.y);
            a.z = fmaf(v.z, w, a.z);  a.w = fmaf(v.w, w, a.w);
        }
        #pragma unroll
        for (int kk = 16; kk < 64; ++kk) {
            const float  w = w2p[kk * 128];
            const float4 v = h1t[kq2 * 64 + kk];
            a.x = fmaf(v.x, w, a.x);  a.y = fmaf(v.y, w, a.y);
            a.z = fmaf(v.z, w, a.z);  a.w = fmaf(v.w, w, a.w);
        }
        h2p[t] = a;
    }

    // ---- layer-3 weight prefetch (all 16 iters) before the sync ----
    const int j3  = t & 63;
    const int k83 = t >> 6;                       // 0..7 (16 iters)
    float w3pre[16];
    {
        const float* __restrict__ w3p = W3 + (k83 * 16) * 64 + j3;
        #pragma unroll
        for (int i = 0; i < 16; ++i) w3pre[i] = w3p[i * 64];
    }
    __syncthreads();

    // combine 4 layer-2 partials, +b2, ReLU
    if (t < 128) {
        const float4 p0 = h2p[t],       p1 = h2p[t + 128];
        const float4 p2 = h2p[t + 256], p3 = h2p[t + 384];
        h2t[t] = make_float4(
            fmaxf(p0.x + p1.x + p2.x + p3.x + bj2, 0.f),
            fmaxf(p0.y + p1.y + p2.y + p3.y + bj2, 0.f),
            fmaxf(p0.z + p1.z + p2.z + p3.z + bj2, 0.f),
            fmaxf(p0.w + p1.w + p2.w + p3.w + bj2, 0.f));
    }
    __syncthreads();

    // ---------------- Layer 3: [4 x 128] @ W3[128 x 64], 8-way split-K -----
    {
        float4 a = make_float4(0.f, 0.f, 0.f, 0.f);
        #pragma unroll
        for (int kk = 0; kk < 16; ++kk) {
            const float  w = w3pre[kk];
            const float4 v = h2t[k83 * 16 + kk];
            a.x = fmaf(v.x, w, a.x);  a.y = fmaf(v.y, w, a.y);
            a.z = fmaf(v.z, w, a.z);  a.w = fmaf(v.w, w, a.w);
        }
        h3p[t] = a;
    }
    __syncthreads();

    // combine 8 layer-3 partials, +b3, ReLU
    if (t < 64) {
        float4 s = make_float4(bj3, bj3, bj3, bj3);
        #pragma unroll
        for (int p = 0; p < 8; ++p) {
            const float4 v = h3p[t + 64 * p];
            s.x += v.x; s.y += v.y; s.z += v.z; s.w += v.w;
        }
        h3t[t] = make_float4(fmaxf(s.x, 0.f), fmaxf(s.y, 0.f),
                             fmaxf(s.z, 0.f), fmaxf(s.w, 0.f));
    }
    __syncthreads();

    // ---------------- Layer 4: [4 x 64] @ W4[64 x 1] + b4 (warp 0) ---------
    if (t < 32) {
        const float4 va = h3t[t], vb = h3t[t + 32];
        float a0 = fmaf(va.x, w4a, vb.x * w4b);
        float a1 = fmaf(va.y, w4a, vb.y * w4b);
        float a2 = fmaf(va.z, w4a, vb.z * w4b);
        float a3 = fmaf(va.w, w4a, vb.w * w4b);
        #pragma unroll
        for (int off = 16; off > 0; off >>= 1) {
            a0 += __shfl_down_sync(0xffffffffu, a0, off);
            a1 += __shfl_down_sync(0xffffffffu, a1, off);
            a2 += __shfl_down_sync(0xffffffffu, a2, off);
            a3 += __shfl_down_sync(0xffffffffu, a3, off);
        }
        if (t == 0) {
            out[row0 + 0] = a0 + bb4;
            out[row0 + 1] = a1 + bb4;
            out[row0 + 2] = a2 + bb4;
            out[row0 + 3] = a3 + bb4;
        }
    }
}

extern "C" void kernel_launch(void* const* d_in, const int* in_sizes, int n_in,
                              void* d_out, int out_size)
{
    const int*   user_ids = (const int*)  d_in[0];
    const int*   item_ids = (const int*)  d_in[1];
    const float* W1       = (const float*)d_in[2];
    const float* b1       = (const float*)d_in[3];
    const float* W2       = (const float*)d_in[4];
    const float* b2       = (const float*)d_in[5];
    const float* W3       = (const float*)d_in[6];
    const float* b3       = (const float*)d_in[7];
    const float* W4       = (const float*)d_in[8];
    const float* b4       = (const float*)d_in[9];
    float*       out      = (float*)d_out;

    mlp_fused_kernel<<<BATCH / ROWS, 512>>>(user_ids, item_ids,
                                            W1, b1, W2, b2, W3, b3, W4, b4, out);
}